// round 9
// baseline (speedup 1.0000x reference)
#include <cuda_runtime.h>
#include <cstdint>

#define BB 64
#define CH 128
#define HH 40
#define WW 96
#define NELEM (BB*CH*HH*WW)          // 31,457,280
#define WTOT  (4*5*9*128*128)        // 2,949,120

// Scratch: transposed weights [dir][iter][k][ci][co] and ping-pong y buffers.
__device__ float g_wt[WTOT];
__device__ float g_buf[2][NELEM];

// ---------------------------------------------------------------------------
// One-time weight transpose: w[(it*128+co)*128+ci)*9+k] -> g_wt[((d*5+it)*9+k)*128+ci)*128+co]
// ---------------------------------------------------------------------------
__global__ void transpose_w_kernel(const float* __restrict__ wd, const float* __restrict__ wu,
                                   const float* __restrict__ wr, const float* __restrict__ wl) {
    int tid = blockIdx.x * 256 + threadIdx.x;
    if (tid >= WTOT) return;
    int co = tid & 127;
    int ci = (tid >> 7) & 127;
    int q  = tid >> 14;          // (d*5+it)*9 + k
    int k  = q % 9;
    int r  = q / 9;              // d*5 + it
    int it = r % 5;
    int d  = r / 5;
    const float* w = (d == 0) ? wd : (d == 1) ? wu : (d == 2) ? wr : wl;
    g_wt[tid] = w[((size_t)(it * 128 + co) * 128 + ci) * 9 + k];
}

// ---------------------------------------------------------------------------
// Horizontal conv step (1x9 along W, roll along H): phases D and U.
// CTA per (b, h). smem: inP[128][104] (w-padded by 4), Wsh[64][128] (ci-chunked).
// Thread tile: 8 c_out (4 f32x2 pairs) x 6 w. 256 threads, 2 CTAs/SM.
// ---------------------------------------------------------------------------
#define SMEM_H ((128*104 + 64*128)*4)

__global__ __launch_bounds__(256, 2)
void step_h_kernel(const float* __restrict__ src_ext, float* __restrict__ dst_ext,
                   int src_sel, int dst_sel, int widx, int hshift) {
    const float* src = (src_sel >= 0) ? g_buf[src_sel] : src_ext;
    float*       dst = (dst_sel >= 0) ? g_buf[dst_sel] : dst_ext;
    const float* w9  = g_wt + (size_t)widx * 9 * 128 * 128;

    extern __shared__ float sm[];
    float* inP = sm;                 // [128][104], tap index = w + 4
    float* Wsh = sm + 128 * 104;     // [64][128]

    int b = blockIdx.y, h = blockIdx.x;
    int t = threadIdx.x;
    int hs = h + hshift; if (hs >= HH) hs -= HH;   // in_h = (h + shift) mod 40

    // Load rolled input row: y[b, ci, hs, :] for all ci (float4, coalesced)
    const float* srow = src + ((size_t)b * CH * HH + hs) * WW;
    for (int i = t; i < 128 * 24; i += 256) {
        int ci = i / 24, wv = i % 24;
        float4 v = *(const float4*)(srow + (size_t)ci * HH * WW + wv * 4);
        *(float4*)&inP[ci * 104 + 4 + wv * 4] = v;
    }
    {   // zero pads: 4 floats on each side of every ci row (256 float4 total)
        float4 z4 = make_float4(0.f, 0.f, 0.f, 0.f);
        int ci = t >> 1, side = t & 1;
        *(float4*)&inP[ci * 104 + (side ? 100 : 0)] = z4;
    }

    int tx = t & 15, ty = t >> 4;
    int co0 = tx * 8, w0 = ty * 6;

    unsigned long long acc[4][6];
#pragma unroll
    for (int j = 0; j < 4; ++j)
#pragma unroll
        for (int jj = 0; jj < 6; ++jj) acc[j][jj] = 0ull;

    for (int k = 0; k < 9; ++k) {
        for (int cc = 0; cc < 2; ++cc) {
            __syncthreads();   // protect inP (first iter) / Wsh reuse
            const float4* wsrc = (const float4*)(w9 + (size_t)(k * 128 + cc * 64) * 128);
            float4* wdst = (float4*)Wsh;
#pragma unroll
            for (int i = 0; i < 8; ++i) wdst[t + i * 256] = wsrc[t + i * 256];
            __syncthreads();

            const float* ibase = inP + cc * 64 * 104 + w0 + k;
            const float* wbase = Wsh + co0;
#pragma unroll 4
            for (int cil = 0; cil < 64; ++cil) {
                ulonglong2 a01 = *(const ulonglong2*)(wbase + cil * 128);      // co pairs 0,1
                ulonglong2 a23 = *(const ulonglong2*)(wbase + cil * 128 + 4);  // co pairs 2,3
                const float* ib = ibase + cil * 104;
#pragma unroll
                for (int jj = 0; jj < 6; ++jj) {
                    unsigned int bi = __float_as_uint(ib[jj]);
                    unsigned long long bb;
                    asm("mov.b64 %0, {%1, %1};" : "=l"(bb) : "r"(bi));
                    asm("fma.rn.f32x2 %0, %1, %2, %0;" : "+l"(acc[0][jj]) : "l"(a01.x), "l"(bb));
                    asm("fma.rn.f32x2 %0, %1, %2, %0;" : "+l"(acc[1][jj]) : "l"(a01.y), "l"(bb));
                    asm("fma.rn.f32x2 %0, %1, %2, %0;" : "+l"(acc[2][jj]) : "l"(a23.x), "l"(bb));
                    asm("fma.rn.f32x2 %0, %1, %2, %0;" : "+l"(acc[3][jj]) : "l"(a23.y), "l"(bb));
                }
            }
        }
    }

    // y_out = y + 2*relu(conv)
    size_t ob = (((size_t)b * CH + co0) * HH + h) * WW + w0;
#pragma unroll
    for (int j = 0; j < 4; ++j) {
#pragma unroll
        for (int jj = 0; jj < 6; ++jj) {
            unsigned int lo, hi;
            asm("mov.b64 {%0, %1}, %2;" : "=r"(lo), "=r"(hi) : "l"(acc[j][jj]));
            size_t i0 = ob + (size_t)(2 * j) * HH * WW + jj;
            size_t i1 = i0 + (size_t)HH * WW;
            dst[i0] = src[i0] + 2.0f * fmaxf(__uint_as_float(lo), 0.f);
            dst[i1] = src[i1] + 2.0f * fmaxf(__uint_as_float(hi), 0.f);
        }
    }
}

// ---------------------------------------------------------------------------
// Vertical conv step (9x1 along H, roll along W): phases R and L.
// CTA per (b, 4-wide w tile). smem: inP[64ci][48h][4w] (h-padded by 4, ci-chunked),
// Wsh[64][128]. Thread tile: 4 c_out x 5 h x one aligned w-pair (f32x2 lanes = w).
// 512 threads, 1 CTA/SM.
// ---------------------------------------------------------------------------
#define SMEM_V ((64*48*4 + 64*128)*4)

__global__ __launch_bounds__(512, 1)
void step_v_kernel(const float* __restrict__ src_ext, float* __restrict__ dst_ext,
                   int src_sel, int dst_sel, int widx, int wshift) {
    const float* src = (src_sel >= 0) ? g_buf[src_sel] : src_ext;
    float*       dst = (dst_sel >= 0) ? g_buf[dst_sel] : dst_ext;
    const float* w9  = g_wt + (size_t)widx * 9 * 128 * 128;

    extern __shared__ float sm[];
    float* inP = sm;                 // [64][48][4]
    float* Wsh = sm + 64 * 48 * 4;   // [64][128]

    int b  = blockIdx.y;
    int w0 = blockIdx.x * 4;
    int t  = threadIdx.x;
    int co_g = t & 31, h_g = (t >> 5) & 7, w_g = t >> 8;   // 32 x 8 x 2 = 512
    int co0 = co_g * 4, h0 = h_g * 5;

    int ws[4];
#pragma unroll
    for (int wl = 0; wl < 4; ++wl) {
        int v = w0 + wl + wshift;                           // in_w = (w + shift) mod 96
        ws[wl] = (v >= WW) ? v - WW : v;
    }

    unsigned long long acc[4][5];
#pragma unroll
    for (int j = 0; j < 4; ++j)
#pragma unroll
        for (int jj = 0; jj < 5; ++jj) acc[j][jj] = 0ull;

    for (int cc = 0; cc < 2; ++cc) {
        __syncthreads();   // protect inP reuse across ci-chunks
        // Load rolled input columns: y[b, ci, h, ws[wl]] (sector-coalesced over wl)
        const float* sb = src + ((size_t)b * CH + cc * 64) * HH * WW;
        for (int i = t; i < 64 * 40 * 4; i += 512) {
            int wl  = i & 3;
            int hh  = (i >> 2) % 40;
            int cil = i / 160;
            inP[(cil * 48 + 4 + hh) * 4 + wl] = sb[((size_t)cil * HH + hh) * WW + ws[wl]];
        }
        for (int i = t; i < 64 * 8 * 4; i += 512) {   // zero pads (h rows 0..3 and 44..47)
            int wl  = i & 3;
            int r   = (i >> 2) & 7;
            int cil = i >> 5;
            int hp  = (r < 4) ? r : (r + 40);
            inP[(cil * 48 + hp) * 4 + wl] = 0.f;
        }
        for (int k = 0; k < 9; ++k) {
            __syncthreads();   // inP ready (k==0) / protect Wsh before overwrite
            const float4* wsrc = (const float4*)(w9 + (size_t)(k * 128 + cc * 64) * 128);
            float4* wdst = (float4*)Wsh;
#pragma unroll
            for (int i = 0; i < 4; ++i) wdst[t + i * 512] = wsrc[t + i * 512];
            __syncthreads();

#pragma unroll 2
            for (int cil = 0; cil < 64; ++cil) {
                float4 a4 = *(const float4*)&Wsh[cil * 128 + co0];
                unsigned long long ap0, ap1, ap2, ap3;
                asm("mov.b64 %0, {%1, %1};" : "=l"(ap0) : "r"(__float_as_uint(a4.x)));
                asm("mov.b64 %0, {%1, %1};" : "=l"(ap1) : "r"(__float_as_uint(a4.y)));
                asm("mov.b64 %0, {%1, %1};" : "=l"(ap2) : "r"(__float_as_uint(a4.z)));
                asm("mov.b64 %0, {%1, %1};" : "=l"(ap3) : "r"(__float_as_uint(a4.w)));
                const float* ib = &inP[(cil * 48 + h0 + k) * 4 + w_g * 2];
#pragma unroll
                for (int jj = 0; jj < 5; ++jj) {
                    unsigned long long bb = *(const unsigned long long*)(ib + jj * 4);
                    asm("fma.rn.f32x2 %0, %1, %2, %0;" : "+l"(acc[0][jj]) : "l"(ap0), "l"(bb));
                    asm("fma.rn.f32x2 %0, %1, %2, %0;" : "+l"(acc[1][jj]) : "l"(ap1), "l"(bb));
                    asm("fma.rn.f32x2 %0, %1, %2, %0;" : "+l"(acc[2][jj]) : "l"(ap2), "l"(bb));
                    asm("fma.rn.f32x2 %0, %1, %2, %0;" : "+l"(acc[3][jj]) : "l"(ap3), "l"(bb));
                }
            }
        }
    }

    int wout = w0 + w_g * 2;
    size_t ob = (((size_t)b * CH + co0) * HH + h0) * WW + wout;
#pragma unroll
    for (int j = 0; j < 4; ++j) {
#pragma unroll
        for (int jj = 0; jj < 5; ++jj) {
            unsigned int lo, hi;
            asm("mov.b64 {%0, %1}, %2;" : "=r"(lo), "=r"(hi) : "l"(acc[j][jj]));
            size_t idx = ob + (size_t)j * HH * WW + (size_t)jj * WW;
            dst[idx]     = src[idx]     + 2.0f * fmaxf(__uint_as_float(lo), 0.f);
            dst[idx + 1] = src[idx + 1] + 2.0f * fmaxf(__uint_as_float(hi), 0.f);
        }
    }
}

// ---------------------------------------------------------------------------
// Launcher: weight transpose + 20 chained step kernels, ping-pong buffers.
// Graph-capturable: kernel launches only, no allocs/syncs/copies.
// ---------------------------------------------------------------------------
extern "C" void kernel_launch(void* const* d_in, const int* in_sizes, int n_in,
                              void* d_out, int out_size) {
    const float* x  = (const float*)d_in[0];
    const float* wd = (const float*)d_in[1];
    const float* wu = (const float*)d_in[2];
    const float* wr = (const float*)d_in[3];
    const float* wl = (const float*)d_in[4];
    float* out = (float*)d_out;

    cudaFuncSetAttribute(step_h_kernel, cudaFuncAttributeMaxDynamicSharedMemorySize, SMEM_H);
    cudaFuncSetAttribute(step_v_kernel, cudaFuncAttributeMaxDynamicSharedMemorySize, SMEM_V);

    transpose_w_kernel<<<(WTOT + 255) / 256, 256>>>(wd, wu, wr, wl);

    static const int offH[5] = {1, 2, 5, 10, 20};    // 40 >> (5-i)
    static const int offW[5] = {3, 6, 12, 24, 48};   // 96 >> (5-i)

    int cur_sel = -1;   // step 0 reads external x
    for (int s = 0; s < 20; ++s) {
        int dst_sel = (s == 19) ? -1 : (s & 1);      // final step writes d_out
        int dir = s / 5, it = s % 5;
        int widx = dir * 5 + it;
        if (dir < 2) {
            // D: in_h=(h+off)%40 ; U: in_h=(h-off)%40 == shift 40-off
            int shift = (dir == 0) ? offH[it] : HH - offH[it];
            step_h_kernel<<<dim3(HH, BB), 256, SMEM_H>>>(x, out, cur_sel, dst_sel, widx, shift);
        } else {
            // R: in_w=(w+off)%96 ; L: shift 96-off
            int shift = (dir == 2) ? offW[it] : WW - offW[it];
            step_v_kernel<<<dim3(WW / 4, BB), 512, SMEM_V>>>(x, out, cur_sel, dst_sel, widx, shift);
        }
        cur_sel = dst_sel;
    }
}

// round 10
// speedup vs baseline: 1.0002x; 1.0002x over previous
#include <cuda_runtime.h>
#include <cstdint>

#define BB 64
#define CH 128
#define HH 40
#define WW 96
#define NELEM (BB*CH*HH*WW)          // 31,457,280
#define WTOT  (4*5*9*128*128)        // 2,949,120

// Scratch: transposed weights [dir][iter][k][ci][co] and ping-pong y buffers.
__device__ float g_wt[WTOT];
__device__ float g_buf[2][NELEM];

// ---------------------------------------------------------------------------
// One-time weight transpose: w[(it*128+co)*128+ci)*9+k] -> g_wt[((d*5+it)*9+k)*128+ci)*128+co]
// ---------------------------------------------------------------------------
__global__ void transpose_w_kernel(const float* __restrict__ wd, const float* __restrict__ wu,
                                   const float* __restrict__ wr, const float* __restrict__ wl) {
    int tid = blockIdx.x * 256 + threadIdx.x;
    if (tid >= WTOT) return;
    int co = tid & 127;
    int ci = (tid >> 7) & 127;
    int q  = tid >> 14;          // (d*5+it)*9 + k
    int k  = q % 9;
    int r  = q / 9;              // d*5 + it
    int it = r % 5;
    int d  = r / 5;
    const float* w = (d == 0) ? wd : (d == 1) ? wu : (d == 2) ? wr : wl;
    g_wt[tid] = w[((size_t)(it * 128 + co) * 128 + ci) * 9 + k];
}

// ---------------------------------------------------------------------------
// Horizontal conv step (1x9 along W, roll along H): phases D and U.
// CTA per (b, h). smem: inP[128][104] (w-padded by 4), Wsh[64][128] (ci-chunked).
// Thread tile: 8 c_out (4 f32x2 pairs) x 6 w. 256 threads, 2 CTAs/SM.
// ---------------------------------------------------------------------------
#define SMEM_H ((128*104 + 64*128)*4)

__global__ __launch_bounds__(256, 2)
void step_h_kernel(const float* __restrict__ src_ext, float* __restrict__ dst_ext,
                   int src_sel, int dst_sel, int widx, int hshift) {
    const float* src = (src_sel >= 0) ? g_buf[src_sel] : src_ext;
    float*       dst = (dst_sel >= 0) ? g_buf[dst_sel] : dst_ext;
    const float* w9  = g_wt + (size_t)widx * 9 * 128 * 128;

    extern __shared__ float sm[];
    float* inP = sm;                 // [128][104], tap index = w + 4
    float* Wsh = sm + 128 * 104;     // [64][128]

    int b = blockIdx.y, h = blockIdx.x;
    int t = threadIdx.x;
    int hs = h + hshift; if (hs >= HH) hs -= HH;   // in_h = (h + shift) mod 40

    // Load rolled input row: y[b, ci, hs, :] for all ci (float4, coalesced)
    const float* srow = src + ((size_t)b * CH * HH + hs) * WW;
    for (int i = t; i < 128 * 24; i += 256) {
        int ci = i / 24, wv = i % 24;
        float4 v = *(const float4*)(srow + (size_t)ci * HH * WW + wv * 4);
        *(float4*)&inP[ci * 104 + 4 + wv * 4] = v;
    }
    {   // zero pads: 4 floats on each side of every ci row (256 float4 total)
        float4 z4 = make_float4(0.f, 0.f, 0.f, 0.f);
        int ci = t >> 1, side = t & 1;
        *(float4*)&inP[ci * 104 + (side ? 100 : 0)] = z4;
    }

    int tx = t & 15, ty = t >> 4;
    int co0 = tx * 8, w0 = ty * 6;

    unsigned long long acc[4][6];
#pragma unroll
    for (int j = 0; j < 4; ++j)
#pragma unroll
        for (int jj = 0; jj < 6; ++jj) acc[j][jj] = 0ull;

    for (int k = 0; k < 9; ++k) {
        for (int cc = 0; cc < 2; ++cc) {
            __syncthreads();   // protect inP (first iter) / Wsh reuse
            const float4* wsrc = (const float4*)(w9 + (size_t)(k * 128 + cc * 64) * 128);
            float4* wdst = (float4*)Wsh;
#pragma unroll
            for (int i = 0; i < 8; ++i) wdst[t + i * 256] = wsrc[t + i * 256];
            __syncthreads();

            const float* ibase = inP + cc * 64 * 104 + w0 + k;
            const float* wbase = Wsh + co0;
#pragma unroll 4
            for (int cil = 0; cil < 64; ++cil) {
                ulonglong2 a01 = *(const ulonglong2*)(wbase + cil * 128);      // co pairs 0,1
                ulonglong2 a23 = *(const ulonglong2*)(wbase + cil * 128 + 4);  // co pairs 2,3
                const float* ib = ibase + cil * 104;
#pragma unroll
                for (int jj = 0; jj < 6; ++jj) {
                    unsigned int bi = __float_as_uint(ib[jj]);
                    unsigned long long bb;
                    asm("mov.b64 %0, {%1, %1};" : "=l"(bb) : "r"(bi));
                    asm("fma.rn.f32x2 %0, %1, %2, %0;" : "+l"(acc[0][jj]) : "l"(a01.x), "l"(bb));
                    asm("fma.rn.f32x2 %0, %1, %2, %0;" : "+l"(acc[1][jj]) : "l"(a01.y), "l"(bb));
                    asm("fma.rn.f32x2 %0, %1, %2, %0;" : "+l"(acc[2][jj]) : "l"(a23.x), "l"(bb));
                    asm("fma.rn.f32x2 %0, %1, %2, %0;" : "+l"(acc[3][jj]) : "l"(a23.y), "l"(bb));
                }
            }
        }
    }

    // y_out = y + 2*relu(conv)
    size_t ob = (((size_t)b * CH + co0) * HH + h) * WW + w0;
#pragma unroll
    for (int j = 0; j < 4; ++j) {
#pragma unroll
        for (int jj = 0; jj < 6; ++jj) {
            unsigned int lo, hi;
            asm("mov.b64 {%0, %1}, %2;" : "=r"(lo), "=r"(hi) : "l"(acc[j][jj]));
            size_t i0 = ob + (size_t)(2 * j) * HH * WW + jj;
            size_t i1 = i0 + (size_t)HH * WW;
            dst[i0] = src[i0] + 2.0f * fmaxf(__uint_as_float(lo), 0.f);
            dst[i1] = src[i1] + 2.0f * fmaxf(__uint_as_float(hi), 0.f);
        }
    }
}

// ---------------------------------------------------------------------------
// Vertical conv step (9x1 along H, roll along W): phases R and L.
// CTA per (b, 4-wide w tile). smem: inP[64ci][48h][4w] (h-padded by 4, ci-chunked),
// Wsh[64][128]. Thread tile: 4 c_out x 5 h x one aligned w-pair (f32x2 lanes = w).
// 512 threads, 1 CTA/SM.
// ---------------------------------------------------------------------------
#define SMEM_V ((64*48*4 + 64*128)*4)

__global__ __launch_bounds__(512, 1)
void step_v_kernel(const float* __restrict__ src_ext, float* __restrict__ dst_ext,
                   int src_sel, int dst_sel, int widx, int wshift) {
    const float* src = (src_sel >= 0) ? g_buf[src_sel] : src_ext;
    float*       dst = (dst_sel >= 0) ? g_buf[dst_sel] : dst_ext;
    const float* w9  = g_wt + (size_t)widx * 9 * 128 * 128;

    extern __shared__ float sm[];
    float* inP = sm;                 // [64][48][4]
    float* Wsh = sm + 64 * 48 * 4;   // [64][128]

    int b  = blockIdx.y;
    int w0 = blockIdx.x * 4;
    int t  = threadIdx.x;
    int co_g = t & 31, h_g = (t >> 5) & 7, w_g = t >> 8;   // 32 x 8 x 2 = 512
    int co0 = co_g * 4, h0 = h_g * 5;

    int ws[4];
#pragma unroll
    for (int wl = 0; wl < 4; ++wl) {
        int v = w0 + wl + wshift;                           // in_w = (w + shift) mod 96
        ws[wl] = (v >= WW) ? v - WW : v;
    }

    unsigned long long acc[4][5];
#pragma unroll
    for (int j = 0; j < 4; ++j)
#pragma unroll
        for (int jj = 0; jj < 5; ++jj) acc[j][jj] = 0ull;

    for (int cc = 0; cc < 2; ++cc) {
        __syncthreads();   // protect inP reuse across ci-chunks
        // Load rolled input columns: y[b, ci, h, ws[wl]] (sector-coalesced over wl)
        const float* sb = src + ((size_t)b * CH + cc * 64) * HH * WW;
        for (int i = t; i < 64 * 40 * 4; i += 512) {
            int wl  = i & 3;
            int hh  = (i >> 2) % 40;
            int cil = i / 160;
            inP[(cil * 48 + 4 + hh) * 4 + wl] = sb[((size_t)cil * HH + hh) * WW + ws[wl]];
        }
        for (int i = t; i < 64 * 8 * 4; i += 512) {   // zero pads (h rows 0..3 and 44..47)
            int wl  = i & 3;
            int r   = (i >> 2) & 7;
            int cil = i >> 5;
            int hp  = (r < 4) ? r : (r + 40);
            inP[(cil * 48 + hp) * 4 + wl] = 0.f;
        }
        for (int k = 0; k < 9; ++k) {
            __syncthreads();   // inP ready (k==0) / protect Wsh before overwrite
            const float4* wsrc = (const float4*)(w9 + (size_t)(k * 128 + cc * 64) * 128);
            float4* wdst = (float4*)Wsh;
#pragma unroll
            for (int i = 0; i < 4; ++i) wdst[t + i * 512] = wsrc[t + i * 512];
            __syncthreads();

#pragma unroll 2
            for (int cil = 0; cil < 64; ++cil) {
                float4 a4 = *(const float4*)&Wsh[cil * 128 + co0];
                unsigned long long ap0, ap1, ap2, ap3;
                asm("mov.b64 %0, {%1, %1};" : "=l"(ap0) : "r"(__float_as_uint(a4.x)));
                asm("mov.b64 %0, {%1, %1};" : "=l"(ap1) : "r"(__float_as_uint(a4.y)));
                asm("mov.b64 %0, {%1, %1};" : "=l"(ap2) : "r"(__float_as_uint(a4.z)));
                asm("mov.b64 %0, {%1, %1};" : "=l"(ap3) : "r"(__float_as_uint(a4.w)));
                const float* ib = &inP[(cil * 48 + h0 + k) * 4 + w_g * 2];
#pragma unroll
                for (int jj = 0; jj < 5; ++jj) {
                    unsigned long long bb = *(const unsigned long long*)(ib + jj * 4);
                    asm("fma.rn.f32x2 %0, %1, %2, %0;" : "+l"(acc[0][jj]) : "l"(ap0), "l"(bb));
                    asm("fma.rn.f32x2 %0, %1, %2, %0;" : "+l"(acc[1][jj]) : "l"(ap1), "l"(bb));
                    asm("fma.rn.f32x2 %0, %1, %2, %0;" : "+l"(acc[2][jj]) : "l"(ap2), "l"(bb));
                    asm("fma.rn.f32x2 %0, %1, %2, %0;" : "+l"(acc[3][jj]) : "l"(ap3), "l"(bb));
                }
            }
        }
    }

    int wout = w0 + w_g * 2;
    size_t ob = (((size_t)b * CH + co0) * HH + h0) * WW + wout;
#pragma unroll
    for (int j = 0; j < 4; ++j) {
#pragma unroll
        for (int jj = 0; jj < 5; ++jj) {
            unsigned int lo, hi;
            asm("mov.b64 {%0, %1}, %2;" : "=r"(lo), "=r"(hi) : "l"(acc[j][jj]));
            size_t idx = ob + (size_t)j * HH * WW + (size_t)jj * WW;
            dst[idx]     = src[idx]     + 2.0f * fmaxf(__uint_as_float(lo), 0.f);
            dst[idx + 1] = src[idx + 1] + 2.0f * fmaxf(__uint_as_float(hi), 0.f);
        }
    }
}

// ---------------------------------------------------------------------------
// Launcher: weight transpose + 20 chained step kernels, ping-pong buffers.
// Graph-capturable: kernel launches only, no allocs/syncs/copies.
// ---------------------------------------------------------------------------
extern "C" void kernel_launch(void* const* d_in, const int* in_sizes, int n_in,
                              void* d_out, int out_size) {
    const float* x  = (const float*)d_in[0];
    const float* wd = (const float*)d_in[1];
    const float* wu = (const float*)d_in[2];
    const float* wr = (const float*)d_in[3];
    const float* wl = (const float*)d_in[4];
    float* out = (float*)d_out;

    cudaFuncSetAttribute(step_h_kernel, cudaFuncAttributeMaxDynamicSharedMemorySize, SMEM_H);
    cudaFuncSetAttribute(step_v_kernel, cudaFuncAttributeMaxDynamicSharedMemorySize, SMEM_V);

    transpose_w_kernel<<<(WTOT + 255) / 256, 256>>>(wd, wu, wr, wl);

    static const int offH[5] = {1, 2, 5, 10, 20};    // 40 >> (5-i)
    static const int offW[5] = {3, 6, 12, 24, 48};   // 96 >> (5-i)

    int cur_sel = -1;   // step 0 reads external x
    for (int s = 0; s < 20; ++s) {
        int dst_sel = (s == 19) ? -1 : (s & 1);      // final step writes d_out
        int dir = s / 5, it = s % 5;
        int widx = dir * 5 + it;
        if (dir < 2) {
            // D: in_h=(h+off)%40 ; U: in_h=(h-off)%40 == shift 40-off
            int shift = (dir == 0) ? offH[it] : HH - offH[it];
            step_h_kernel<<<dim3(HH, BB), 256, SMEM_H>>>(x, out, cur_sel, dst_sel, widx, shift);
        } else {
            // R: in_w=(w+off)%96 ; L: shift 96-off
            int shift = (dir == 2) ? offW[it] : WW - offW[it];
            step_v_kernel<<<dim3(WW / 4, BB), 512, SMEM_V>>>(x, out, cur_sel, dst_sel, widx, shift);
        }
        cur_sel = dst_sel;
    }
}